// round 15
// baseline (speedup 1.0000x reference)
#include <cuda_runtime.h>
#include <cstdint>
#include <cstddef>

#define NROWS 16384
#define HID   4096
#define EPSV  1e-5f

// Column split: scalar CSA-8 path [0, CSPLIT), IMMA path [CSPLIT, 4096)
#define CSPLIT   3328
#define TILES_S  (CSPLIT / 64)          // 52 scalar tiles (64 cols)
#define TILES_T  ((HID - CSPLIT) / 128) // 6 imma tiles (128 cols)

// ---------------------------------------------------------------------------
// Scratch (device globals; no allocation allowed)
// ---------------------------------------------------------------------------
__device__ __align__(16) uint32_t g_xb  [NROWS * 24];    // input bits, row-major
__device__ __align__(16) uint32_t g_act0[NROWS * 128];   // act bits ping
__device__ __align__(16) uint32_t g_act1[NROWS * 128];   // act bits pong
__device__ __align__(16) uint32_t g_wb1 [24  * 4096];    // W1 bits K-major
__device__ __align__(16) uint32_t g_wb2 [128 * 4096];
__device__ __align__(16) uint32_t g_wb3 [128 * 4096];
__device__ __align__(16) uint32_t g_wb4 [16  * 128];     // W4 bits row-major
__device__ __align__(16) uint8_t  g_xb8 [NROWS * 768];           // input ±1 s8
__device__ __align__(16) uint8_t  g_a8_0[(size_t)NROWS * HID];   // act ±1 s8 ping
__device__ __align__(16) uint8_t  g_a8_1[(size_t)NROWS * HID];   // act ±1 s8 pong
__device__ __align__(16) uint8_t  g_w8_1[(size_t)HID * 768];     // W ±1 s8 row-major
__device__ __align__(16) uint8_t  g_w8_2[(size_t)HID * HID];
__device__ __align__(16) uint8_t  g_w8_3[(size_t)HID * HID];

// ---------------------------------------------------------------------------
// Helpers
// ---------------------------------------------------------------------------
__device__ __forceinline__ uint32_t xor3(uint32_t a, uint32_t b, uint32_t c) {
    uint32_t r;
    asm("lop3.b32 %0, %1, %2, %3, 0x96;" : "=r"(r) : "r"(a), "r"(b), "r"(c));
    return r;
}
__device__ __forceinline__ uint32_t maj3(uint32_t a, uint32_t b, uint32_t c) {
    uint32_t r;
    asm("lop3.b32 %0, %1, %2, %3, 0xE8;" : "=r"(r) : "r"(a), "r"(b), "r"(c));
    return r;
}
__device__ __forceinline__ void imad_acc(uint32_t& acc, uint32_t p, uint32_t w) {
    asm("mad.lo.u32 %0, %1, %2, %0;" : "+r"(acc) : "r"(p), "r"(w));
}
__device__ __forceinline__ uint32_t smem_u32(const void* p) {
    uint32_t a;
    asm("{ .reg .u64 t; cvta.to.shared.u64 t, %1; cvt.u32.u64 %0, t; }" : "=r"(a) : "l"(p));
    return a;
}
__device__ __forceinline__ void cp_async16(uint32_t dst, const void* src) {
    asm volatile("cp.async.cg.shared.global [%0], [%1], 16;" :: "r"(dst), "l"(src) : "memory");
}
#define CP_COMMIT() asm volatile("cp.async.commit_group;" ::: "memory")
#define CP_WAIT0()  asm volatile("cp.async.wait_group 0;" ::: "memory")
#define CP_WAIT1()  asm volatile("cp.async.wait_group 1;" ::: "memory")
__device__ __forceinline__ void ldsm_x4(uint32_t (&r)[4], uint32_t addr) {
    asm volatile("ldmatrix.sync.aligned.m8n8.x4.shared.b16 {%0,%1,%2,%3}, [%4];"
                 : "=r"(r[0]), "=r"(r[1]), "=r"(r[2]), "=r"(r[3]) : "r"(addr));
}
__device__ __forceinline__ void mma_s8(uint32_t (&d)[4], const uint32_t (&a)[4],
                                       uint32_t b0, uint32_t b1) {
    asm volatile(
        "mma.sync.aligned.m16n8k32.row.col.s32.s8.s8.s32 "
        "{%0,%1,%2,%3}, {%4,%5,%6,%7}, {%8,%9}, {%0,%1,%2,%3};"
        : "+r"(d[0]), "+r"(d[1]), "+r"(d[2]), "+r"(d[3])
        : "r"(a[0]), "r"(a[1]), "r"(a[2]), "r"(a[3]), "r"(b0), "r"(b1));
}
// pack 4 flag bytes -> word of ±1 s8
__device__ __forceinline__ uint32_t flags_to_s8(const uint8_t* f) {
    uint32_t w = 0;
#pragma unroll
    for (int b = 0; b < 4; ++b) w |= (f[b] ? 0xFFu : 0x01u) << (8 * b);
    return w;
}

// ---------------------------------------------------------------------------
// Binarize (bit = x<0; x>=0 -> +1 incl. -0.0). Emits bit format and,
// if dst8 != null, row-major ±1 s8 bytes in the same pass.
// ---------------------------------------------------------------------------
__global__ void binarize_kernel(const float* __restrict__ src, uint32_t* __restrict__ dst,
                                uint8_t* __restrict__ dst8,
                                int rows, int kwords, int stride) {
    int wg   = (blockIdx.x * blockDim.x + threadIdx.x) >> 5;
    int lane = threadIdx.x & 31;
    if (wg >= rows) return;
    const float* p = src + (size_t)wg * (size_t)stride;
    for (int w = 0; w < kwords; ++w) {
        bool neg = p[w * 32 + lane] < 0.0f;
        unsigned bits = __ballot_sync(0xffffffffu, neg);
        if (lane == 0) dst[(size_t)wg * kwords + w] = bits;
        if (dst8) dst8[(size_t)wg * (kwords * 32) + w * 32 + lane] = neg ? 0xFF : 0x01;
    }
}
// K-major bits (dst[w][row]) + optional row-major s8 bytes
__global__ void binarize_T_kernel(const float* __restrict__ src, uint32_t* __restrict__ dst,
                                  uint8_t* __restrict__ dst8,
                                  int rows, int kwords, int stride, int ncols) {
    int wg   = (blockIdx.x * blockDim.x + threadIdx.x) >> 5;
    int lane = threadIdx.x & 31;
    if (wg >= rows) return;
    const float* p = src + (size_t)wg * (size_t)stride;
    for (int w = 0; w < kwords; ++w) {
        bool neg = p[w * 32 + lane] < 0.0f;
        unsigned bits = __ballot_sync(0xffffffffu, neg);
        if (lane == 0) dst[(size_t)w * ncols + wg] = bits;
        if (dst8) dst8[(size_t)wg * (kwords * 32) + w * 32 + lane] = neg ? 0xFF : 0x01;
    }
}

// ---------------------------------------------------------------------------
// HYBRID layer kernel: one launch, two CTA species by blockIdx.x.
//   bx < TILES_S : scalar CSA-8 bit-GEMM (R8-validated, 64-col tile)
//   bx >= TILES_S: s8 IMMA GEMM (R3-validated, 128-col tile, tensor pipe)
// Both produce exact integer dots -> identical BN threshold -> dual-format out.
// ---------------------------------------------------------------------------
#define RSTR    80
#define ISTAGE  (128 * RSTR)      // 10240 B per operand per stage (imma)

template<int KW, int KCH>
__global__ void __launch_bounds__(256, 2) hybrid_kernel(
        const uint32_t* __restrict__ Ab,  // act bits, row-major [*, KW]
        const uint32_t* __restrict__ Wt,  // W bits, K-major [KW][4096]
        const uint8_t*  __restrict__ A8,  // act ±1 s8, row-major [*, K]
        const uint8_t*  __restrict__ W8,  // W ±1 s8, row-major [4096][K]
        const float* __restrict__ bias, const float* __restrict__ gam,
        const float* __restrict__ bet,  const float* __restrict__ mean,
        const float* __restrict__ var,
        uint32_t* __restrict__ Ob, uint8_t* __restrict__ O8,
        int Kfull, uint32_t oneArg) {
    __shared__ __align__(16) unsigned char smem[49152];
    const uint32_t sb = smem_u32(smem);
    const int tid = threadIdx.x;
    const int rowBase = blockIdx.y * 128;

    if (blockIdx.x < TILES_S) {
        // ================= scalar CSA-8 path (R8 text, byte-out added) =====
        constexpr int A_BYTES = 128 * KCH * 4;
        constexpr int W_BYTES = KCH * 64 * 4;
        constexpr int STAGE   = A_BYTES + W_BYTES;
        constexpr int NB      = KCH / 8;
        constexpr int NC      = KW / KCH;

        const int colBase = blockIdx.x * 64;
        const int tx = tid & 15, ty = tid >> 4;
        const uint32_t w1m = oneArg, w2m = oneArg + oneArg, w4m = w2m + w2m;

        uint32_t acc[8][4];
#pragma unroll
        for (int i = 0; i < 8; ++i)
#pragma unroll
            for (int j = 0; j < 4; ++j) acc[i][j] = 0u;

        constexpr int NA = 128 * (KCH / 4);
        constexpr int NW = KCH * 16;

        auto load_chunk = [&](int s, int kb) {
            const uint32_t base = sb + (uint32_t)s * STAGE;
#pragma unroll 2
            for (int idx = tid; idx < NA + NW; idx += 256) {
                if (idx < NA) {
                    int r = idx / (KCH / 4), g = idx - r * (KCH / 4);
                    cp_async16(base + (uint32_t)(r * KCH + g * 4) * 4,
                               Ab + (size_t)(rowBase + r) * KW + kb + g * 4);
                } else {
                    int idx2 = idx - NA;
                    int k = idx2 >> 4, g = idx2 & 15;
                    cp_async16(base + A_BYTES + (uint32_t)(k * 64 + g * 4) * 4,
                               Wt + (size_t)(kb + k) * 4096 + colBase + g * 4);
                }
            }
            CP_COMMIT();
        };

        load_chunk(0, 0);
        for (int c = 0; c < NC; ++c) {
            CP_WAIT0();
            __syncthreads();
            if (c + 1 < NC) load_chunk((c + 1) & 1, (c + 1) * KCH);

            const unsigned char* sA = smem + (c & 1) * STAGE;
            const unsigned char* sW = sA + A_BYTES;
#pragma unroll
            for (int b = 0; b < NB; ++b) {
                const int k8 = b * 8;
                uint4 w8r[8];
#pragma unroll
                for (int k = 0; k < 8; ++k)
                    w8r[k] = *(const uint4*)(sW + (size_t)(k8 + k) * 256 + tx * 16);
#pragma unroll
                for (int i = 0; i < 8; ++i) {
                    const unsigned char* ar = sA + (size_t)(ty * 8 + i) * (KCH * 4) + k8 * 4;
                    uint4 alo = *(const uint4*)(ar);
                    uint4 ahi = *(const uint4*)(ar + 16);
                    uint32_t aw[8] = {alo.x, alo.y, alo.z, alo.w, ahi.x, ahi.y, ahi.z, ahi.w};
#pragma unroll
                    for (int j = 0; j < 4; ++j) {
                        uint32_t x0 = aw[0] ^ ((const uint32_t*)&w8r[0])[j];
                        uint32_t x1 = aw[1] ^ ((const uint32_t*)&w8r[1])[j];
                        uint32_t x2 = aw[2] ^ ((const uint32_t*)&w8r[2])[j];
                        uint32_t x3 = aw[3] ^ ((const uint32_t*)&w8r[3])[j];
                        uint32_t x4 = aw[4] ^ ((const uint32_t*)&w8r[4])[j];
                        uint32_t x5 = aw[5] ^ ((const uint32_t*)&w8r[5])[j];
                        uint32_t x6 = aw[6] ^ ((const uint32_t*)&w8r[6])[j];
                        uint32_t x7 = aw[7] ^ ((const uint32_t*)&w8r[7])[j];
                        uint32_t s1 = xor3(x0, x1, x2), c1 = maj3(x0, x1, x2);
                        uint32_t s2 = xor3(x3, x4, x5), c2 = maj3(x3, x4, x5);
                        uint32_t s3 = xor3(s1, s2, x6), c3 = maj3(s1, s2, x6);
                        uint32_t s4 = xor3(c1, c2, c3), c4 = maj3(c1, c2, c3);
                        imad_acc(acc[i][j], (uint32_t)__popc(s3), w1m);
                        imad_acc(acc[i][j], (uint32_t)__popc(x7), w1m);
                        imad_acc(acc[i][j], (uint32_t)__popc(s4), w2m);
                        imad_acc(acc[i][j], (uint32_t)__popc(c4), w4m);
                    }
                }
            }
            __syncthreads();
        }

        uint8_t* flags = (uint8_t*)smem;   // 8KB
#pragma unroll
        for (int j = 0; j < 4; ++j) {
            int n = colBase + tx * 4 + j;
            float scale = __fmul_rn(gam[n], rsqrtf(__fadd_rn(var[n], EPSV)));
            float mn = mean[n], bt = bet[n], bs = bias[n];
#pragma unroll
            for (int i = 0; i < 8; ++i) {
                float hf = __fadd_rn((float)(Kfull - 2 * (int)acc[i][j]), bs);
                float f  = __fadd_rn(__fmul_rn(__fsub_rn(hf, mn), scale), bt);
                flags[(ty * 8 + i) * 64 + tx * 4 + j] = (f < 0.0f) ? 1 : 0;
            }
        }
        __syncthreads();
        {
            int r = tid >> 1, cw = tid & 1;
            const uint8_t* fr = flags + r * 64 + cw * 32;
            uint32_t wbits = 0u;
#pragma unroll
            for (int i = 0; i < 32; ++i) wbits |= ((uint32_t)fr[i]) << i;
            Ob[(size_t)(rowBase + r) * 128 + (colBase >> 5) + cw] = wbits;
            uint32_t bw[8];
#pragma unroll
            for (int g = 0; g < 8; ++g) bw[g] = flags_to_s8(fr + g * 4);
            uint4* d8 = (uint4*)(O8 + (size_t)(rowBase + r) * HID + colBase + cw * 32);
            d8[0] = make_uint4(bw[0], bw[1], bw[2], bw[3]);
            d8[1] = make_uint4(bw[4], bw[5], bw[6], bw[7]);
        }
    } else {
        // ================= IMMA path (R3-validated mainloop) ================
        const int colBase = CSPLIT + (blockIdx.x - TILES_S) * 128;
        const int lane = tid & 31, wid = tid >> 5;
        const int warpM = wid & 3, warpN = wid >> 2;
        const int K = Kfull;
        const int NC = K >> 6;

        const int j  = lane >> 3, r8 = lane & 7;
        const int jr = ((j & 1) << 3) + r8;
        const uint32_t khalf = (uint32_t)((j >> 1) << 4);

        uint32_t aBase[2], bBase[4];
#pragma unroll
        for (int m = 0; m < 2; ++m)
            aBase[m] = sb + (uint32_t)(warpM * 32 + m * 16 + jr) * RSTR + khalf;
#pragma unroll
        for (int p = 0; p < 4; ++p)
            bBase[p] = sb + 2 * ISTAGE + (uint32_t)(warpN * 64 + p * 16 + jr) * RSTR + khalf;

        uint32_t d[2][8][4];
#pragma unroll
        for (int m = 0; m < 2; ++m)
#pragma unroll
            for (int n = 0; n < 8; ++n)
#pragma unroll
                for (int q = 0; q < 4; ++q) d[m][n][q] = 0u;

        const int ldRow = tid >> 2, ldCh = (tid & 3) << 4;
        const uint8_t* gA  = A8 + (size_t)(rowBase + ldRow) * K + ldCh;
        const uint8_t* gA2 = A8 + (size_t)(rowBase + ldRow + 64) * K + ldCh;
        const uint8_t* gB  = W8 + (size_t)(colBase + ldRow) * K + ldCh;
        const uint8_t* gB2 = W8 + (size_t)(colBase + ldRow + 64) * K + ldCh;
        const uint32_t sA0 = sb + (uint32_t)ldRow * RSTR + ldCh;
        const uint32_t sA1 = sb + (uint32_t)(ldRow + 64) * RSTR + ldCh;
        const uint32_t sB0 = sb + 2 * ISTAGE + (uint32_t)ldRow * RSTR + ldCh;
        const uint32_t sB1 = sb + 2 * ISTAGE + (uint32_t)(ldRow + 64) * RSTR + ldCh;

        cp_async16(sA0, gA);
        cp_async16(sA1, gA2);
        cp_async16(sB0, gB);
        cp_async16(sB1, gB2);
        CP_COMMIT();

        for (int c = 0; c < NC; ++c) {
            if (c + 1 < NC) {
                const uint32_t so = (uint32_t)((c + 1) & 1) * ISTAGE;
                const int ko = (c + 1) << 6;
                cp_async16(sA0 + so, gA + ko);
                cp_async16(sA1 + so, gA2 + ko);
                cp_async16(sB0 + so, gB + ko);
                cp_async16(sB1 + so, gB2 + ko);
                CP_COMMIT();
                CP_WAIT1();
            } else {
                CP_WAIT0();
            }
            __syncthreads();

            const uint32_t so = (uint32_t)(c & 1) * ISTAGE;
#pragma unroll
            for (int ks = 0; ks < 2; ++ks) {
                const uint32_t ko = so + (uint32_t)(ks << 5);
                uint32_t af[2][4], bf[4][4];
#pragma unroll
                for (int m = 0; m < 2; ++m) ldsm_x4(af[m], aBase[m] + ko);
#pragma unroll
                for (int p = 0; p < 4; ++p) ldsm_x4(bf[p], bBase[p] + ko);
#pragma unroll
                for (int m = 0; m < 2; ++m)
#pragma unroll
                    for (int n = 0; n < 8; ++n) {
                        const int p = n >> 1, h = n & 1;
                        mma_s8(d[m][n], af[m], bf[p][h], bf[p][h + 2]);
                    }
            }
            __syncthreads();
        }

        // BN threshold -> flags in smem (dual-format pack)
        uint8_t* flags = (uint8_t*)smem;   // 16KB
        {
            const int rl0 = warpM * 32 + (lane >> 2);
            const int cl0 = warpN * 64 + ((lane & 3) << 1);
#pragma unroll
            for (int n = 0; n < 8; ++n) {
                const int cl = cl0 + n * 8;
                const int cg = colBase + cl;
                float sc0 = __fmul_rn(gam[cg],     rsqrtf(__fadd_rn(var[cg],     EPSV)));
                float sc1 = __fmul_rn(gam[cg + 1], rsqrtf(__fadd_rn(var[cg + 1], EPSV)));
                float mn0 = mean[cg], bt0 = bet[cg], bs0 = bias[cg];
                float mn1 = mean[cg + 1], bt1 = bet[cg + 1], bs1 = bias[cg + 1];
#pragma unroll
                for (int m = 0; m < 2; ++m)
#pragma unroll
                    for (int rh = 0; rh < 2; ++rh) {
                        const int rl = rl0 + m * 16 + rh * 8;
                        float h0 = __fadd_rn((float)(int)d[m][n][rh * 2 + 0], bs0);
                        float h1 = __fadd_rn((float)(int)d[m][n][rh * 2 + 1], bs1);
                        float f0 = __fadd_rn(__fmul_rn(__fsub_rn(h0, mn0), sc0), bt0);
                        float f1 = __fadd_rn(__fmul_rn(__fsub_rn(h1, mn1), sc1), bt1);
                        flags[rl * 128 + cl]     = (f0 < 0.0f) ? 1 : 0;
                        flags[rl * 128 + cl + 1] = (f1 < 0.0f) ? 1 : 0;
                    }
            }
        }
        __syncthreads();
#pragma unroll
        for (int it = 0; it < 2; ++it) {
            int idx = tid + it * 256;
            int r = idx >> 2, cw = idx & 3;
            const uint8_t* fr = flags + r * 128 + cw * 32;
            uint32_t wbits = 0u;
#pragma unroll
            for (int i = 0; i < 32; ++i) wbits |= ((uint32_t)fr[i]) << i;
            Ob[(size_t)(rowBase + r) * 128 + (colBase >> 5) + cw] = wbits;
            uint32_t bw[8];
#pragma unroll
            for (int g = 0; g < 8; ++g) bw[g] = flags_to_s8(fr + g * 4);
            uint4* d8 = (uint4*)(O8 + (size_t)(rowBase + r) * HID + colBase + cw * 32);
            d8[0] = make_uint4(bw[0], bw[1], bw[2], bw[3]);
            d8[1] = make_uint4(bw[4], bw[5], bw[6], bw[7]);
        }
    }
}

// ---------------------------------------------------------------------------
// Layer 4 (4096 -> 10) + BN + log_softmax. One warp per row (bit format).
// ---------------------------------------------------------------------------
__global__ void final_kernel(const uint32_t* __restrict__ A, const uint32_t* __restrict__ W4,
                             const float* __restrict__ bias, const float* __restrict__ gam,
                             const float* __restrict__ bet,  const float* __restrict__ mean,
                             const float* __restrict__ var,  float* __restrict__ out) {
    int wg   = (blockIdx.x * blockDim.x + threadIdx.x) >> 5;
    int lane = threadIdx.x & 31;
    if (wg >= NROWS) return;

    uint32_t aw[4];
#pragma unroll
    for (int j = 0; j < 4; ++j) aw[j] = A[(size_t)wg * 128 + j * 32 + lane];

    float f[10];
#pragma unroll
    for (int o = 0; o < 10; ++o) {
        uint32_t c = 0u;
#pragma unroll
        for (int j = 0; j < 4; ++j) c += (uint32_t)__popc(aw[j] ^ W4[o * 128 + j * 32 + lane]);
        uint32_t tot = __reduce_add_sync(0xffffffffu, c);
        float hf    = __fadd_rn((float)(4096 - 2 * (int)tot), bias[o]);
        float scale = __fmul_rn(gam[o], rsqrtf(__fadd_rn(var[o], EPSV)));
        f[o] = __fadd_rn(__fmul_rn(__fsub_rn(hf, mean[o]), scale), bet[o]);
    }
    float mx = f[0];
#pragma unroll
    for (int o = 1; o < 10; ++o) mx = fmaxf(mx, f[o]);
    float s = 0.0f;
#pragma unroll
    for (int o = 0; o < 10; ++o) s += expf(f[o] - mx);
    float lse = logf(s);
    if (lane < 10) out[(size_t)wg * 10 + lane] = (f[lane] - mx) - lse;
}

// ---------------------------------------------------------------------------
extern "C" void kernel_launch(void* const* d_in, const int* in_sizes, int n_in,
                              void* d_out, int out_size) {
    (void)in_sizes; (void)n_in; (void)out_size;
    const float* x  = (const float*)d_in[0];
    const float* w1 = (const float*)d_in[1];
    const float* b1 = (const float*)d_in[2];
    const float* g1 = (const float*)d_in[3];
    const float* be1= (const float*)d_in[4];
    const float* m1 = (const float*)d_in[5];
    const float* v1 = (const float*)d_in[6];
    const float* w2 = (const float*)d_in[7];
    const float* b2 = (const float*)d_in[8];
    const float* g2 = (const float*)d_in[9];
    const float* be2= (const float*)d_in[10];
    const float* m2 = (const float*)d_in[11];
    const float* v2 = (const float*)d_in[12];
    const float* w3 = (const float*)d_in[13];
    const float* b3 = (const float*)d_in[14];
    const float* g3 = (const float*)d_in[15];
    const float* be3= (const float*)d_in[16];
    const float* m3 = (const float*)d_in[17];
    const float* v3 = (const float*)d_in[18];
    const float* w4 = (const float*)d_in[19];
    const float* b4 = (const float*)d_in[20];
    const float* g4 = (const float*)d_in[21];
    const float* be4= (const float*)d_in[22];
    const float* m4 = (const float*)d_in[23];
    const float* v4 = (const float*)d_in[24];
    float* out = (float*)d_out;

    uint32_t *xb, *a0, *a1, *wb1, *wb2, *wb3, *wb4;
    uint8_t *xb8, *a80, *a81, *pw81, *pw82, *pw83;
    cudaGetSymbolAddress((void**)&xb,  g_xb);
    cudaGetSymbolAddress((void**)&a0,  g_act0);
    cudaGetSymbolAddress((void**)&a1,  g_act1);
    cudaGetSymbolAddress((void**)&wb1, g_wb1);
    cudaGetSymbolAddress((void**)&wb2, g_wb2);
    cudaGetSymbolAddress((void**)&wb3, g_wb3);
    cudaGetSymbolAddress((void**)&wb4, g_wb4);
    cudaGetSymbolAddress((void**)&xb8, g_xb8);
    cudaGetSymbolAddress((void**)&a80, g_a8_0);
    cudaGetSymbolAddress((void**)&a81, g_a8_1);
    cudaGetSymbolAddress((void**)&pw81, g_w8_1);
    cudaGetSymbolAddress((void**)&pw82, g_w8_2);
    cudaGetSymbolAddress((void**)&pw83, g_w8_3);

    // Binarize: dual-format where IMMA needs bytes
    binarize_kernel  <<<(NROWS * 32) / 256, 256>>>(x,  xb,  xb8, NROWS, 24, 784);
    binarize_T_kernel<<<(4096  * 32) / 256, 256>>>(w1, wb1, pw81, 4096, 24, 768, 4096);
    binarize_T_kernel<<<(4096  * 32) / 256, 256>>>(w2, wb2, pw82, 4096, 128, 4096, 4096);
    binarize_T_kernel<<<(4096  * 32) / 256, 256>>>(w3, wb3, pw83, 4096, 128, 4096, 4096);
    binarize_kernel  <<<2, 256>>>(w4, wb4, (uint8_t*)nullptr, 10, 128, 4096);

    dim3 grid(TILES_S + TILES_T, NROWS / 128);
    // L1: K=768
    hybrid_kernel<24, 8><<<grid, 256>>>(xb, wb1, xb8, pw81,
                                        b1, g1, be1, m1, v1, a0, a80, 768, 1u);
    // L2/L3: K=4096
    hybrid_kernel<128, 32><<<grid, 256>>>(a0, wb2, a80, pw82,
                                          b2, g2, be2, m2, v2, a1, a81, 4096, 1u);
    hybrid_kernel<128, 32><<<grid, 256>>>(a1, wb3, a81, pw83,
                                          b3, g3, be3, m3, v3, a0, a80, 4096, 1u);
    // L4 + log_softmax
    final_kernel<<<(NROWS * 32) / 256, 256>>>(a0, wb4, b4, g4, be4, m4, v4, out);
}

// round 16
// speedup vs baseline: 1.3344x; 1.3344x over previous
#include <cuda_runtime.h>
#include <cstdint>
#include <cstddef>

#define NROWS 16384
#define HID   4096
#define EPSV  1e-5f

// ---------------------------------------------------------------------------
// Scratch (device globals; no allocation allowed)
// ---------------------------------------------------------------------------
__device__ __align__(16) uint32_t g_xb  [NROWS * 24];    // binarized input, row-major [16384][24]
__device__ __align__(16) uint32_t g_act0[NROWS * 128];   // packed activations ping (row-major)
__device__ __align__(16) uint32_t g_act1[NROWS * 128];   // packed activations pong
__device__ __align__(16) uint32_t g_wb1 [24  * 4096];    // W1 binarized K-MAJOR [24][4096]
__device__ __align__(16) uint32_t g_wb2 [128 * 4096];    // W2 K-major [128][4096]
__device__ __align__(16) uint32_t g_wb3 [128 * 4096];    // W3 K-major [128][4096]
__device__ __align__(16) uint32_t g_wb4 [16  * 128];     // W4 row-major [10][128]

// ---------------------------------------------------------------------------
// LOP3 helpers (alu pipe) + IMAD accumulate (fma pipe) + cp.async
// ---------------------------------------------------------------------------
__device__ __forceinline__ uint32_t xor3(uint32_t a, uint32_t b, uint32_t c) {
    uint32_t r;
    asm("lop3.b32 %0, %1, %2, %3, 0x96;" : "=r"(r) : "r"(a), "r"(b), "r"(c));
    return r;
}
__device__ __forceinline__ uint32_t maj3(uint32_t a, uint32_t b, uint32_t c) {
    uint32_t r;
    asm("lop3.b32 %0, %1, %2, %3, 0xE8;" : "=r"(r) : "r"(a), "r"(b), "r"(c));
    return r;
}
__device__ __forceinline__ void imad_acc(uint32_t& acc, uint32_t p, uint32_t w) {
    asm("mad.lo.u32 %0, %1, %2, %0;" : "+r"(acc) : "r"(p), "r"(w));
}
__device__ __forceinline__ uint32_t smem_u32(const void* p) {
    uint32_t a;
    asm("{ .reg .u64 t; cvta.to.shared.u64 t, %1; cvt.u32.u64 %0, t; }" : "=r"(a) : "l"(p));
    return a;
}
__device__ __forceinline__ void cp_async16(uint32_t dst, const void* src) {
    asm volatile("cp.async.cg.shared.global [%0], [%1], 16;" :: "r"(dst), "l"(src) : "memory");
}
#define CP_COMMIT() asm volatile("cp.async.commit_group;" ::: "memory")
#define CP_WAIT0()  asm volatile("cp.async.wait_group 0;" ::: "memory")

// ---------------------------------------------------------------------------
// Binarize row-major: dst[row][w]  (bit = x<0; x>=0 -> +1 incl. -0.0)
// ---------------------------------------------------------------------------
__global__ void binarize_kernel(const float* __restrict__ src, uint32_t* __restrict__ dst,
                                int rows, int kwords, int stride) {
    int wg   = (blockIdx.x * blockDim.x + threadIdx.x) >> 5;
    int lane = threadIdx.x & 31;
    if (wg >= rows) return;
    const float* p = src + (size_t)wg * (size_t)stride;
    for (int w = 0; w < kwords; ++w) {
        unsigned bits = __ballot_sync(0xffffffffu, p[w * 32 + lane] < 0.0f);
        if (lane == 0) dst[(size_t)wg * kwords + w] = bits;
    }
}
// Binarize K-major (transposed): dst[w][row]
__global__ void binarize_T_kernel(const float* __restrict__ src, uint32_t* __restrict__ dst,
                                  int rows, int kwords, int stride, int ncols) {
    int wg   = (blockIdx.x * blockDim.x + threadIdx.x) >> 5;
    int lane = threadIdx.x & 31;
    if (wg >= rows) return;
    const float* p = src + (size_t)wg * (size_t)stride;
    for (int w = 0; w < kwords; ++w) {
        unsigned bits = __ballot_sync(0xffffffffu, p[w * 32 + lane] < 0.0f);
        if (lane == 0) dst[(size_t)w * ncols + wg] = bits;
    }
}

// ---------------------------------------------------------------------------
// Bit-GEMM (CSA-8) + BN-threshold + repack, cp.async double-buffered.
// CTA tile 128 rows x 64 cols, 256 threads, 8x4 outputs/thread.
// VALIDATED R8 kernel — loop ordering WAIT0 -> sync -> issue-next -> compute.
// ---------------------------------------------------------------------------
template<int KW, int KCH>
__global__ void __launch_bounds__(256, 2) bitgemm_kernel(
        const uint32_t* __restrict__ A,   // row-major [*, KW]
        const uint32_t* __restrict__ Wt,  // K-major  [KW][4096]
        const float* __restrict__ bias, const float* __restrict__ gam,
        const float* __restrict__ bet,  const float* __restrict__ mean,
        const float* __restrict__ var,  uint32_t* __restrict__ O, int Kfull,
        uint32_t oneArg) {
    constexpr int A_BYTES = 128 * KCH * 4;          // A stage bytes
    constexpr int W_BYTES = KCH * 64 * 4;           // W stage bytes
    constexpr int STAGE   = A_BYTES + W_BYTES;
    constexpr int NB      = KCH / 8;                // k8-blocks per chunk
    constexpr int NC      = KW / KCH;               // chunks
    __shared__ __align__(16) unsigned char smem[2 * STAGE];
    const uint32_t sb = smem_u32(smem);

    const int tid     = threadIdx.x;
    const int rowBase = blockIdx.y * 128;
    const int colBase = blockIdx.x * 64;
    const int tx = tid & 15;   // -> 4 cols (contiguous in K-major W)
    const int ty = tid >> 4;   // -> 8 rows

    const uint32_t w1m = oneArg;           // 1 (opaque to ptxas)
    const uint32_t w2m = oneArg + oneArg;  // 2
    const uint32_t w4m = w2m + w2m;        // 4

    uint32_t acc[8][4];
#pragma unroll
    for (int i = 0; i < 8; ++i)
#pragma unroll
        for (int j = 0; j < 4; ++j) acc[i][j] = 0u;

    constexpr int NA = 128 * (KCH / 4);             // A 16B-chunks per stage
    constexpr int NW = KCH * 16;                    // W 16B-chunks per stage

    // chunk loader (cp.async): stage s, k-offset kb
    auto load_chunk = [&](int s, int kb) {
        const uint32_t base = sb + (uint32_t)s * STAGE;
#pragma unroll 2
        for (int idx = tid; idx < NA + NW; idx += 256) {
            if (idx < NA) {
                int r = idx / (KCH / 4), g = idx - r * (KCH / 4);
                cp_async16(base + (uint32_t)(r * KCH + g * 4) * 4,
                           A + (size_t)(rowBase + r) * KW + kb + g * 4);
            } else {
                int idx2 = idx - NA;
                int k = idx2 >> 4, g = idx2 & 15;
                cp_async16(base + A_BYTES + (uint32_t)(k * 64 + g * 4) * 4,
                           Wt + (size_t)(kb + k) * 4096 + colBase + g * 4);
            }
        }
        CP_COMMIT();
    };

    load_chunk(0, 0);

    for (int c = 0; c < NC; ++c) {
        CP_WAIT0();                       // wait chunk c (only group outstanding)
        __syncthreads();                  // visible to all; prev stage free
        if (c + 1 < NC) load_chunk((c + 1) & 1, (c + 1) * KCH);   // fly during compute

        const unsigned char* sA = smem + (c & 1) * STAGE;
        const unsigned char* sW = sA + A_BYTES;

#pragma unroll
        for (int b = 0; b < NB; ++b) {
            const int k8 = b * 8;
            // W: 8 LDS.128 -> 4 contiguous cols x 8 k
            uint4 w8[8];
#pragma unroll
            for (int k = 0; k < 8; ++k)
                w8[k] = *(const uint4*)(sW + (size_t)(k8 + k) * 256 + tx * 16);

#pragma unroll
            for (int i = 0; i < 8; ++i) {
                const unsigned char* ar = sA + (size_t)(ty * 8 + i) * (KCH * 4) + k8 * 4;
                uint4 alo = *(const uint4*)(ar);
                uint4 ahi = *(const uint4*)(ar + 16);
                uint32_t aw[8] = {alo.x, alo.y, alo.z, alo.w, ahi.x, ahi.y, ahi.z, ahi.w};
#pragma unroll
                for (int j = 0; j < 4; ++j) {
                    uint32_t x0 = aw[0] ^ ((const uint32_t*)&w8[0])[j];
                    uint32_t x1 = aw[1] ^ ((const uint32_t*)&w8[1])[j];
                    uint32_t x2 = aw[2] ^ ((const uint32_t*)&w8[2])[j];
                    uint32_t x3 = aw[3] ^ ((const uint32_t*)&w8[3])[j];
                    uint32_t x4 = aw[4] ^ ((const uint32_t*)&w8[4])[j];
                    uint32_t x5 = aw[5] ^ ((const uint32_t*)&w8[5])[j];
                    uint32_t x6 = aw[6] ^ ((const uint32_t*)&w8[6])[j];
                    uint32_t x7 = aw[7] ^ ((const uint32_t*)&w8[7])[j];
                    // CSA-8: ones = popc(s3)+popc(x7)+2*popc(s4)+4*popc(c4)
                    uint32_t s1 = xor3(x0, x1, x2), c1 = maj3(x0, x1, x2);
                    uint32_t s2 = xor3(x3, x4, x5), c2 = maj3(x3, x4, x5);
                    uint32_t s3 = xor3(s1, s2, x6), c3 = maj3(s1, s2, x6);
                    uint32_t s4 = xor3(c1, c2, c3), c4 = maj3(c1, c2, c3);
                    uint32_t p1 = (uint32_t)__popc(s3);
                    uint32_t p2 = (uint32_t)__popc(x7);
                    uint32_t p3 = (uint32_t)__popc(s4);
                    uint32_t p4 = (uint32_t)__popc(c4);
                    imad_acc(acc[i][j], p1, w1m);   // fma pipe
                    imad_acc(acc[i][j], p2, w1m);
                    imad_acc(acc[i][j], p3, w2m);
                    imad_acc(acc[i][j], p4, w4m);
                }
            }
        }
        __syncthreads();                  // compute done before stage overwrite next iter
    }

    // Epilogue: BN threshold -> flag bytes in (reused) shared memory
    uint8_t* flags = (uint8_t*)smem;   // 8KB needed, fits
#pragma unroll
    for (int j = 0; j < 4; ++j) {
        int n = colBase + tx * 4 + j;
        float scale = __fmul_rn(gam[n], rsqrtf(__fadd_rn(var[n], EPSV)));
        float mn = mean[n], bt = bet[n], bs = bias[n];
#pragma unroll
        for (int i = 0; i < 8; ++i) {
            float hf = __fadd_rn((float)(Kfull - 2 * (int)acc[i][j]), bs);
            float f  = __fadd_rn(__fmul_rn(__fsub_rn(hf, mn), scale), bt);
            flags[(ty * 8 + i) * 64 + tx * 4 + j] = (f < 0.0f) ? (uint8_t)1 : (uint8_t)0;
        }
    }
    __syncthreads();

    // Pack: 128 rows x 2 output words = 256 words, one per thread (row-major out)
    {
        int r = tid >> 1, cw = tid & 1;
        const uint8_t* fr = flags + r * 64 + cw * 32;
        uint32_t wbits = 0u;
#pragma unroll
        for (int i = 0; i < 32; ++i) wbits |= ((uint32_t)fr[i]) << i;
        O[(size_t)(rowBase + r) * 128 + (colBase >> 5) + cw] = wbits;
    }
}

// ---------------------------------------------------------------------------
// Layer 4 (4096 -> 10) + BN + log_softmax. One warp per row. (row-major A)
// ---------------------------------------------------------------------------
__global__ void final_kernel(const uint32_t* __restrict__ A, const uint32_t* __restrict__ W4,
                             const float* __restrict__ bias, const float* __restrict__ gam,
                             const float* __restrict__ bet,  const float* __restrict__ mean,
                             const float* __restrict__ var,  float* __restrict__ out) {
    int wg   = (blockIdx.x * blockDim.x + threadIdx.x) >> 5;
    int lane = threadIdx.x & 31;
    if (wg >= NROWS) return;

    uint32_t aw[4];
#pragma unroll
    for (int j = 0; j < 4; ++j) aw[j] = A[(size_t)wg * 128 + j * 32 + lane];

    float f[10];
#pragma unroll
    for (int o = 0; o < 10; ++o) {
        uint32_t c = 0u;
#pragma unroll
        for (int j = 0; j < 4; ++j) c += (uint32_t)__popc(aw[j] ^ W4[o * 128 + j * 32 + lane]);
        uint32_t tot = __reduce_add_sync(0xffffffffu, c);
        float hf    = __fadd_rn((float)(4096 - 2 * (int)tot), bias[o]);
        float scale = __fmul_rn(gam[o], rsqrtf(__fadd_rn(var[o], EPSV)));
        f[o] = __fadd_rn(__fmul_rn(__fsub_rn(hf, mean[o]), scale), bet[o]);
    }
    float mx = f[0];
#pragma unroll
    for (int o = 1; o < 10; ++o) mx = fmaxf(mx, f[o]);
    float s = 0.0f;
#pragma unroll
    for (int o = 0; o < 10; ++o) s += expf(f[o] - mx);
    float lse = logf(s);
    if (lane < 10) out[(size_t)wg * 10 + lane] = (f[lane] - mx) - lse;
}

// ---------------------------------------------------------------------------
extern "C" void kernel_launch(void* const* d_in, const int* in_sizes, int n_in,
                              void* d_out, int out_size) {
    (void)in_sizes; (void)n_in; (void)out_size;
    const float* x  = (const float*)d_in[0];
    const float* w1 = (const float*)d_in[1];
    const float* b1 = (const float*)d_in[2];
    const float* g1 = (const float*)d_in[3];
    const float* be1= (const float*)d_in[4];
    const float* m1 = (const float*)d_in[5];
    const float* v1 = (const float*)d_in[6];
    const float* w2 = (const float*)d_in[7];
    const float* b2 = (const float*)d_in[8];
    const float* g2 = (const float*)d_in[9];
    const float* be2= (const float*)d_in[10];
    const float* m2 = (const float*)d_in[11];
    const float* v2 = (const float*)d_in[12];
    const float* w3 = (const float*)d_in[13];
    const float* b3 = (const float*)d_in[14];
    const float* g3 = (const float*)d_in[15];
    const float* be3= (const float*)d_in[16];
    const float* m3 = (const float*)d_in[17];
    const float* v3 = (const float*)d_in[18];
    const float* w4 = (const float*)d_in[19];
    const float* b4 = (const float*)d_in[20];
    const float* g4 = (const float*)d_in[21];
    const float* be4= (const float*)d_in[22];
    const float* m4 = (const float*)d_in[23];
    const float* v4 = (const float*)d_in[24];
    float* out = (float*)d_out;

    uint32_t *xb, *a0, *a1, *wb1, *wb2, *wb3, *wb4;
    cudaGetSymbolAddress((void**)&xb,  g_xb);
    cudaGetSymbolAddress((void**)&a0,  g_act0);
    cudaGetSymbolAddress((void**)&a1,  g_act1);
    cudaGetSymbolAddress((void**)&wb1, g_wb1);
    cudaGetSymbolAddress((void**)&wb2, g_wb2);
    cudaGetSymbolAddress((void**)&wb3, g_wb3);
    cudaGetSymbolAddress((void**)&wb4, g_wb4);

    // Side stream + events, created once on the first (non-captured) call.
    // No device memory is allocated. Cross-stream work is expressed via
    // events so graph capture follows the dependencies.
    static cudaStream_t s2 = nullptr;
    static cudaEvent_t evFork = nullptr, evJoin = nullptr;
    if (s2 == nullptr) {
        cudaStreamCreateWithFlags(&s2, cudaStreamNonBlocking);
        cudaEventCreateWithFlags(&evFork, cudaEventDisableTiming);
        cudaEventCreateWithFlags(&evJoin, cudaEventDisableTiming);
    }

    // Fork: w2/w3/w4 binarize (needed only from L2 onward) run on s2,
    // overlapped with binarize-x/w1 and the L1 GEMM on the main stream.
    cudaEventRecord(evFork, 0);
    cudaStreamWaitEvent(s2, evFork, 0);
    binarize_T_kernel<<<(4096 * 32) / 256, 256, 0, s2>>>(w2, wb2, 4096, 128, 4096, 4096);
    binarize_T_kernel<<<(4096 * 32) / 256, 256, 0, s2>>>(w3, wb3, 4096, 128, 4096, 4096);
    binarize_kernel  <<<2, 256, 0, s2>>>(w4, wb4, 10, 128, 4096);
    cudaEventRecord(evJoin, s2);

    // Main stream: inputs for L1, then L1
    binarize_kernel  <<<(NROWS * 32) / 256, 256>>>(x,  xb,  NROWS, 24, 784);
    binarize_T_kernel<<<(4096  * 32) / 256, 256>>>(w1, wb1, 4096, 24, 768, 4096);

    dim3 grid(4096 / 64, NROWS / 128);
    // L1: K=768 (24 words, single chunk) — R8-validated
    bitgemm_kernel<24, 24><<<grid, 256>>>(xb, wb1, b1, g1, be1, m1, v1, a0, 768, 1u);

    // Join: L2 needs wb2 (and later wb3/wb4)
    cudaStreamWaitEvent(0, evJoin, 0);

    // L2/L3: K=4096 (4 chunks of 32, 2-stage) — R8-validated
    bitgemm_kernel<128, 32><<<grid, 256>>>(a0, wb2, b2, g2, be2, m2, v2, a1, 4096, 1u);
    bitgemm_kernel<128, 32><<<grid, 256>>>(a1, wb3, b3, g3, be3, m3, v3, a0, 4096, 1u);
    // L4 + log_softmax
    final_kernel<<<(NROWS * 32) / 256, 256>>>(a0, wb4, b4, g4, be4, m4, v4, out);
}

// round 17
// speedup vs baseline: 1.3386x; 1.0032x over previous
#include <cuda_runtime.h>
#include <cstdint>
#include <cstddef>

#define NROWS 16384
#define HID   4096
#define EPSV  1e-5f

// ---------------------------------------------------------------------------
// Scratch (device globals; no allocation allowed)
// ---------------------------------------------------------------------------
__device__ __align__(16) uint32_t g_xb  [NROWS * 24];    // binarized input, row-major [16384][24]
__device__ __align__(16) uint32_t g_act0[NROWS * 128];   // packed activations ping (row-major)
__device__ __align__(16) uint32_t g_act1[NROWS * 128];   // packed activations pong
__device__ __align__(16) uint32_t g_wb1 [24  * 4096];    // W1 binarized K-MAJOR [24][4096]
__device__ __align__(16) uint32_t g_wb2 [128 * 4096];    // W2 K-major [128][4096]
__device__ __align__(16) uint32_t g_wb3 [128 * 4096];    // W3 K-major [128][4096]
__device__ __align__(16) uint32_t g_wb4 [16  * 128];     // W4 row-major [10][128]

// ---------------------------------------------------------------------------
// LOP3 helpers (alu pipe) + IMAD accumulate (fma pipe) + cp.async
// ---------------------------------------------------------------------------
__device__ __forceinline__ uint32_t xor3(uint32_t a, uint32_t b, uint32_t c) {
    uint32_t r;
    asm("lop3.b32 %0, %1, %2, %3, 0x96;" : "=r"(r) : "r"(a), "r"(b), "r"(c));
    return r;
}
__device__ __forceinline__ uint32_t maj3(uint32_t a, uint32_t b, uint32_t c) {
    uint32_t r;
    asm("lop3.b32 %0, %1, %2, %3, 0xE8;" : "=r"(r) : "r"(a), "r"(b), "r"(c));
    return r;
}
__device__ __forceinline__ void imad_acc(uint32_t& acc, uint32_t p, uint32_t w) {
    asm("mad.lo.u32 %0, %1, %2, %0;" : "+r"(acc) : "r"(p), "r"(w));
}
__device__ __forceinline__ uint32_t smem_u32(const void* p) {
    uint32_t a;
    asm("{ .reg .u64 t; cvta.to.shared.u64 t, %1; cvt.u32.u64 %0, t; }" : "=r"(a) : "l"(p));
    return a;
}
__device__ __forceinline__ void cp_async16(uint32_t dst, const void* src) {
    asm volatile("cp.async.cg.shared.global [%0], [%1], 16;" :: "r"(dst), "l"(src) : "memory");
}
#define CP_COMMIT() asm volatile("cp.async.commit_group;" ::: "memory")
#define CP_WAIT0()  asm volatile("cp.async.wait_group 0;" ::: "memory")

// ---------------------------------------------------------------------------
// Binarize row-major: dst[row][w]  (bit = x<0; x>=0 -> +1 incl. -0.0)
// ---------------------------------------------------------------------------
__global__ void binarize_kernel(const float* __restrict__ src, uint32_t* __restrict__ dst,
                                int rows, int kwords, int stride) {
    int wg   = (blockIdx.x * blockDim.x + threadIdx.x) >> 5;
    int lane = threadIdx.x & 31;
    if (wg >= rows) return;
    const float* p = src + (size_t)wg * (size_t)stride;
    for (int w = 0; w < kwords; ++w) {
        unsigned bits = __ballot_sync(0xffffffffu, p[w * 32 + lane] < 0.0f);
        if (lane == 0) dst[(size_t)wg * kwords + w] = bits;
    }
}
// Binarize K-major (transposed): dst[w][row]
__global__ void binarize_T_kernel(const float* __restrict__ src, uint32_t* __restrict__ dst,
                                  int rows, int kwords, int stride, int ncols) {
    int wg   = (blockIdx.x * blockDim.x + threadIdx.x) >> 5;
    int lane = threadIdx.x & 31;
    if (wg >= rows) return;
    const float* p = src + (size_t)wg * (size_t)stride;
    for (int w = 0; w < kwords; ++w) {
        unsigned bits = __ballot_sync(0xffffffffu, p[w * 32 + lane] < 0.0f);
        if (lane == 0) dst[(size_t)w * ncols + wg] = bits;
    }
}

// ---------------------------------------------------------------------------
// Bit-GEMM (CSA-8) + BN-threshold + repack, cp.async double-buffered.
// CTA tile 128 rows x 64 cols, 256 threads, 8x4 outputs/thread.
// Loop: WAIT0 -> sync[B] -> issue-next -> compute. The former end-of-iteration
// barrier is REMOVED: loads at iter c overwrite stage (c+1)&1, last read at
// compute(c-1); every warp issues those loads only after passing [B] at iter c,
// and [B] requires all warps to have finished compute(c-1) (program order),
// so [B] alone carries the anti-dependency.
// ---------------------------------------------------------------------------
template<int KW, int KCH>
__global__ void __launch_bounds__(256, 2) bitgemm_kernel(
        const uint32_t* __restrict__ A,   // row-major [*, KW]
        const uint32_t* __restrict__ Wt,  // K-major  [KW][4096]
        const float* __restrict__ bias, const float* __restrict__ gam,
        const float* __restrict__ bet,  const float* __restrict__ mean,
        const float* __restrict__ var,  uint32_t* __restrict__ O, int Kfull,
        uint32_t oneArg) {
    constexpr int A_BYTES = 128 * KCH * 4;          // A stage bytes
    constexpr int W_BYTES = KCH * 64 * 4;           // W stage bytes
    constexpr int STAGE   = A_BYTES + W_BYTES;
    constexpr int NB      = KCH / 8;                // k8-blocks per chunk
    constexpr int NC      = KW / KCH;               // chunks
    __shared__ __align__(16) unsigned char smem[2 * STAGE];
    const uint32_t sb = smem_u32(smem);

    const int tid     = threadIdx.x;
    const int rowBase = blockIdx.y * 128;
    const int colBase = blockIdx.x * 64;
    const int tx = tid & 15;   // -> 4 cols (contiguous in K-major W)
    const int ty = tid >> 4;   // -> 8 rows

    const uint32_t w1m = oneArg;           // 1 (opaque to ptxas)
    const uint32_t w2m = oneArg + oneArg;  // 2
    const uint32_t w4m = w2m + w2m;        // 4

    uint32_t acc[8][4];
#pragma unroll
    for (int i = 0; i < 8; ++i)
#pragma unroll
        for (int j = 0; j < 4; ++j) acc[i][j] = 0u;

    constexpr int NA = 128 * (KCH / 4);             // A 16B-chunks per stage
    constexpr int NW = KCH * 16;                    // W 16B-chunks per stage

    // chunk loader (cp.async): stage s, k-offset kb
    auto load_chunk = [&](int s, int kb) {
        const uint32_t base = sb + (uint32_t)s * STAGE;
#pragma unroll 2
        for (int idx = tid; idx < NA + NW; idx += 256) {
            if (idx < NA) {
                int r = idx / (KCH / 4), g = idx - r * (KCH / 4);
                cp_async16(base + (uint32_t)(r * KCH + g * 4) * 4,
                           A + (size_t)(rowBase + r) * KW + kb + g * 4);
            } else {
                int idx2 = idx - NA;
                int k = idx2 >> 4, g = idx2 & 15;
                cp_async16(base + A_BYTES + (uint32_t)(k * 64 + g * 4) * 4,
                           Wt + (size_t)(kb + k) * 4096 + colBase + g * 4);
            }
        }
        CP_COMMIT();
    };

    load_chunk(0, 0);

    for (int c = 0; c < NC; ++c) {
        CP_WAIT0();                       // wait chunk c (only group outstanding)
        __syncthreads();                  // [B]: chunk c visible; all warps past compute(c-1)
        if (c + 1 < NC) load_chunk((c + 1) & 1, (c + 1) * KCH);   // fly during compute

        const unsigned char* sA = smem + (c & 1) * STAGE;
        const unsigned char* sW = sA + A_BYTES;

#pragma unroll
        for (int b = 0; b < NB; ++b) {
            const int k8 = b * 8;
            // W: 8 LDS.128 -> 4 contiguous cols x 8 k
            uint4 w8[8];
#pragma unroll
            for (int k = 0; k < 8; ++k)
                w8[k] = *(const uint4*)(sW + (size_t)(k8 + k) * 256 + tx * 16);

#pragma unroll
            for (int i = 0; i < 8; ++i) {
                const unsigned char* ar = sA + (size_t)(ty * 8 + i) * (KCH * 4) + k8 * 4;
                uint4 alo = *(const uint4*)(ar);
                uint4 ahi = *(const uint4*)(ar + 16);
                uint32_t aw[8] = {alo.x, alo.y, alo.z, alo.w, ahi.x, ahi.y, ahi.z, ahi.w};
#pragma unroll
                for (int j = 0; j < 4; ++j) {
                    uint32_t x0 = aw[0] ^ ((const uint32_t*)&w8[0])[j];
                    uint32_t x1 = aw[1] ^ ((const uint32_t*)&w8[1])[j];
                    uint32_t x2 = aw[2] ^ ((const uint32_t*)&w8[2])[j];
                    uint32_t x3 = aw[3] ^ ((const uint32_t*)&w8[3])[j];
                    uint32_t x4 = aw[4] ^ ((const uint32_t*)&w8[4])[j];
                    uint32_t x5 = aw[5] ^ ((const uint32_t*)&w8[5])[j];
                    uint32_t x6 = aw[6] ^ ((const uint32_t*)&w8[6])[j];
                    uint32_t x7 = aw[7] ^ ((const uint32_t*)&w8[7])[j];
                    // CSA-8: ones = popc(s3)+popc(x7)+2*popc(s4)+4*popc(c4)
                    uint32_t s1 = xor3(x0, x1, x2), c1 = maj3(x0, x1, x2);
                    uint32_t s2 = xor3(x3, x4, x5), c2 = maj3(x3, x4, x5);
                    uint32_t s3 = xor3(s1, s2, x6), c3 = maj3(s1, s2, x6);
                    uint32_t s4 = xor3(c1, c2, c3), c4 = maj3(c1, c2, c3);
                    uint32_t p1 = (uint32_t)__popc(s3);
                    uint32_t p2 = (uint32_t)__popc(x7);
                    uint32_t p3 = (uint32_t)__popc(s4);
                    uint32_t p4 = (uint32_t)__popc(c4);
                    imad_acc(acc[i][j], p1, w1m);   // fma pipe
                    imad_acc(acc[i][j], p2, w1m);
                    imad_acc(acc[i][j], p3, w2m);
                    imad_acc(acc[i][j], p4, w4m);
                }
            }
        }
        // (former end-of-iteration __syncthreads removed — see header comment)
    }
    __syncthreads();                      // all compute done before flags reuse smem

    // Epilogue: BN threshold -> flag bytes in (reused) shared memory
    uint8_t* flags = (uint8_t*)smem;   // 8KB needed, fits
#pragma unroll
    for (int j = 0; j < 4; ++j) {
        int n = colBase + tx * 4 + j;
        float scale = __fmul_rn(gam[n], rsqrtf(__fadd_rn(var[n], EPSV)));
        float mn = mean[n], bt = bet[n], bs = bias[n];
#pragma unroll
        for (int i = 0; i < 8; ++i) {
            float hf = __fadd_rn((float)(Kfull - 2 * (int)acc[i][j]), bs);
            float f  = __fadd_rn(__fmul_rn(__fsub_rn(hf, mn), scale), bt);
            flags[(ty * 8 + i) * 64 + tx * 4 + j] = (f < 0.0f) ? (uint8_t)1 : (uint8_t)0;
        }
    }
    __syncthreads();

    // Pack: 128 rows x 2 output words = 256 words, one per thread (row-major out)
    {
        int r = tid >> 1, cw = tid & 1;
        const uint8_t* fr = flags + r * 64 + cw * 32;
        uint32_t wbits = 0u;
#pragma unroll
        for (int i = 0; i < 32; ++i) wbits |= ((uint32_t)fr[i]) << i;
        O[(size_t)(rowBase + r) * 128 + (colBase >> 5) + cw] = wbits;
    }
}

// ---------------------------------------------------------------------------
// Layer 4 (4096 -> 10) + BN + log_softmax. One warp per row. (row-major A)
// ---------------------------------------------------------------------------
__global__ void final_kernel(const uint32_t* __restrict__ A, const uint32_t* __restrict__ W4,
                             const float* __restrict__ bias, const float* __restrict__ gam,
                             const float* __restrict__ bet,  const float* __restrict__ mean,
                             const float* __restrict__ var,  float* __restrict__ out) {
    int wg   = (blockIdx.x * blockDim.x + threadIdx.x) >> 5;
    int lane = threadIdx.x & 31;
    if (wg >= NROWS) return;

    uint32_t aw[4];
#pragma unroll
    for (int j = 0; j < 4; ++j) aw[j] = A[(size_t)wg * 128 + j * 32 + lane];

    float f[10];
#pragma unroll
    for (int o = 0; o < 10; ++o) {
        uint32_t c = 0u;
#pragma unroll
        for (int j = 0; j < 4; ++j) c += (uint32_t)__popc(aw[j] ^ W4[o * 128 + j * 32 + lane]);
        uint32_t tot = __reduce_add_sync(0xffffffffu, c);
        float hf    = __fadd_rn((float)(4096 - 2 * (int)tot), bias[o]);
        float scale = __fmul_rn(gam[o], rsqrtf(__fadd_rn(var[o], EPSV)));
        f[o] = __fadd_rn(__fmul_rn(__fsub_rn(hf, mean[o]), scale), bet[o]);
    }
    float mx = f[0];
#pragma unroll
    for (int o = 1; o < 10; ++o) mx = fmaxf(mx, f[o]);
    float s = 0.0f;
#pragma unroll
    for (int o = 0; o < 10; ++o) s += expf(f[o] - mx);
    float lse = logf(s);
    if (lane < 10) out[(size_t)wg * 10 + lane] = (f[lane] - mx) - lse;
}

// ---------------------------------------------------------------------------
extern "C" void kernel_launch(void* const* d_in, const int* in_sizes, int n_in,
                              void* d_out, int out_size) {
    (void)in_sizes; (void)n_in; (void)out_size;
    const float* x  = (const float*)d_in[0];
    const float* w1 = (const float*)d_in[1];
    const float* b1 = (const float*)d_in[2];
    const float* g1 = (const float*)d_in[3];
    const float* be1= (const float*)d_in[4];
    const float* m1 = (const float*)d_in[5];
    const float* v1 = (const float*)d_in[6];
    const float* w2 = (const float*)d_in[7];
    const float* b2 = (const float*)d_in[8];
    const float* g2 = (const float*)d_in[9];
    const float* be2= (const float*)d_in[10];
    const float* m2 = (const float*)d_in[11];
    const float* v2 = (const float*)d_in[12];
    const float* w3 = (const float*)d_in[13];
    const float* b3 = (const float*)d_in[14];
    const float* g3 = (const float*)d_in[15];
    const float* be3= (const float*)d_in[16];
    const float* m3 = (const float*)d_in[17];
    const float* v3 = (const float*)d_in[18];
    const float* w4 = (const float*)d_in[19];
    const float* b4 = (const float*)d_in[20];
    const float* g4 = (const float*)d_in[21];
    const float* be4= (const float*)d_in[22];
    const float* m4 = (const float*)d_in[23];
    const float* v4 = (const float*)d_in[24];
    float* out = (float*)d_out;

    uint32_t *xb, *a0, *a1, *wb1, *wb2, *wb3, *wb4;
    cudaGetSymbolAddress((void**)&xb,  g_xb);
    cudaGetSymbolAddress((void**)&a0,  g_act0);
    cudaGetSymbolAddress((void**)&a1,  g_act1);
    cudaGetSymbolAddress((void**)&wb1, g_wb1);
    cudaGetSymbolAddress((void**)&wb2, g_wb2);
    cudaGetSymbolAddress((void**)&wb3, g_wb3);
    cudaGetSymbolAddress((void**)&wb4, g_wb4);

    // Side stream + events, created once on the first (non-captured) call.
    static cudaStream_t s2 = nullptr;
    static cudaEvent_t evFork = nullptr, evJoin = nullptr;
    if (s2 == nullptr) {
        cudaStreamCreateWithFlags(&s2, cudaStreamNonBlocking);
        cudaEventCreateWithFlags(&evFork, cudaEventDisableTiming);
        cudaEventCreateWithFlags(&evJoin, cudaEventDisableTiming);
    }

    // Fork: w2/w3/w4 binarize (needed only from L2 onward) run on s2,
    // overlapped with binarize-x/w1 and the L1 GEMM on the main stream.
    cudaEventRecord(evFork, 0);
    cudaStreamWaitEvent(s2, evFork, 0);
    binarize_T_kernel<<<(4096 * 32) / 256, 256, 0, s2>>>(w2, wb2, 4096, 128, 4096, 4096);
    binarize_T_kernel<<<(4096 * 32) / 256, 256, 0, s2>>>(w3, wb3, 4096, 128, 4096, 4096);
    binarize_kernel  <<<2, 256, 0, s2>>>(w4, wb4, 10, 128, 4096);
    cudaEventRecord(evJoin, s2);

    // Main stream: inputs for L1, then L1
    binarize_kernel  <<<(NROWS * 32) / 256, 256>>>(x,  xb,  NROWS, 24, 784);
    binarize_T_kernel<<<(4096  * 32) / 256, 256>>>(w1, wb1, 4096, 24, 768, 4096);

    dim3 grid(4096 / 64, NROWS / 128);
    // L1: K=768 (24 words, single chunk)
    bitgemm_kernel<24, 24><<<grid, 256>>>(xb, wb1, b1, g1, be1, m1, v1, a0, 768, 1u);

    // Join: L2 needs wb2 (and later wb3/wb4)
    cudaStreamWaitEvent(0, evJoin, 0);

    // L2/L3: K=4096 (4 chunks of 32, 2-stage)
    bitgemm_kernel<128, 32><<<grid, 256>>>(a0, wb2, b2, g2, be2, m2, v2, a1, 4096, 1u);
    bitgemm_kernel<128, 32><<<grid, 256>>>(a1, wb3, b3, g3, be3, m3, v3, a0, 4096, 1u);
    // L4 + log_softmax
    final_kernel<<<(NROWS * 32) / 256, 256>>>(a0, wb4, b4, g4, be4, m4, v4, out);
}